// round 12
// baseline (speedup 1.0000x reference)
#include <cuda_runtime.h>
#include <cuda_bf16.h>
#include <cstdint>

// Problem constants
#define B_ 64
#define T_ 256
#define H_ 256
#define G4_ 1024      // 4*H
#define KRAW 600      // 2*E
#define KP 640        // padded K (20 chunks of 32)
#define L_ 15
#define M_ (B_*T_)    // 16384

// ------------------------- device scratch (no allocations) -------------------------
__device__ __align__(16) __nv_bfloat16 d_xb[(size_t)M_ * KP];    // [16384, 640] bf16
__device__ __align__(16) __nv_bfloat16 d_wb[(size_t)2048 * KP];  // [2048, 640] bf16
__device__ float d_g[(size_t)2 * M_ * G4_];               // [dir][t(or s)][b][1024]
__device__ float d_h[(size_t)M_ * 2 * H_];                // [b][t][512] = [h_f | h_b]
__device__ float d_emis[(size_t)M_ * L_];                 // [b][t][15]
__device__ float d_hbuf[2 * 8 * 2 * 2048];                // [dir][bbt][buf][unit*8+batch]
__device__ float d_partial[B_];
__device__ unsigned g_flag[128];                          // per-block step counters

// ------------------------- helpers -------------------------
__device__ __forceinline__ float sigm(float x) {
    float e = __expf(-x);
    return __fdividef(1.0f, 1.0f + e);
}
__device__ __forceinline__ float tanh_ap(float x) {
    float y;
    asm("tanh.approx.f32 %0, %1;" : "=f"(y) : "f"(x));
    return y;
}
__device__ __forceinline__ uint32_t smem_u32(const void* p) {
    uint32_t a;
    asm("{ .reg .u64 t; cvta.to.shared.u64 t, %1; cvt.u32.u64 %0, t; }" : "=r"(a) : "l"(p));
    return a;
}
// pack two f32 into bf16x2 (lo = first/lower-k element)
__device__ __forceinline__ uint32_t bf16x2_pack(float hi, float lo) {
    uint32_t r;
    asm("cvt.rn.bf16x2.f32 %0, %1, %2;" : "=r"(r) : "f"(hi), "f"(lo));
    return r;
}
// cp.async helpers (sm_80 base ISA)
__device__ __forceinline__ void cp_async16(uint32_t dst, const void* src) {
    asm volatile("cp.async.cg.shared.global [%0], [%1], 16;" :: "r"(dst), "l"(src));
}
#define CP_COMMIT() asm volatile("cp.async.commit_group;" ::: "memory")
#define CP_WAIT(n)  asm volatile("cp.async.wait_group %0;" :: "n"(n) : "memory")

// ------------------------- K0: reset flags -------------------------
__global__ void k_init() {
    if (threadIdx.x < 128) g_flag[threadIdx.x] = 0u;
}

// ------------------------- K1: embedding gather + concat + bf16 + pad -------------------------
__global__ void k_embed(const int* __restrict__ ids, const int* __restrict__ sids,
                        const float* __restrict__ emb, const float* __restrict__ semb) {
    int m = blockIdx.x;
    int c = threadIdx.x;
    __nv_bfloat16* xp = d_xb + (size_t)m * KP;
    if (c < 300) {
        int id = ids[m];
        int sid = sids[m];
        xp[c]       = __float2bfloat16_rn(emb[(size_t)id * 300 + c]);
        xp[300 + c] = __float2bfloat16_rn(semb[(size_t)sid * 300 + c]);
    } else {
        int z = c - 300;
        xp[600 + z] = __float2bfloat16_rn(0.f);
        xp[620 + z] = __float2bfloat16_rn(0.f);
    }
}

// ------------------------- K1b: weight conversion to bf16 (padded) -------------------------
__global__ void k_wconv(const float* __restrict__ Wf, const float* __restrict__ Wb) {
    int idx = blockIdx.x * blockDim.x + threadIdx.x;
    if (idx >= 2048 * KP) return;
    int row = idx / KP, k = idx - row * KP;
    float v = 0.f;
    if (k < KRAW) v = (row < 1024) ? Wf[row * KRAW + k] : Wb[(row - 1024) * KRAW + k];
    d_wb[idx] = __float2bfloat16_rn(v);
}

// ------------------------- K2: mma.sync bf16 GEMM, cp.async 3-stage (R10/R11, proven) -------------------------
#define APITCH 40
#define STAGE_ELEMS (128 * APITCH)
#define GSMEM_BYTES (3 * 2 * STAGE_ELEMS * 2)

__device__ __forceinline__ void ldm_x4(uint32_t* r, uint32_t addr) {
    asm volatile("ldmatrix.sync.aligned.m8n8.x4.shared.b16 {%0,%1,%2,%3}, [%4];"
                 : "=r"(r[0]), "=r"(r[1]), "=r"(r[2]), "=r"(r[3]) : "r"(addr));
}
__device__ __forceinline__ void mma16816(float* c, const uint32_t* a, const uint32_t* b) {
    asm volatile(
        "mma.sync.aligned.m16n8k16.row.col.f32.bf16.bf16.f32 "
        "{%0,%1,%2,%3}, {%4,%5,%6,%7}, {%8,%9}, {%0,%1,%2,%3};"
        : "+f"(c[0]), "+f"(c[1]), "+f"(c[2]), "+f"(c[3])
        : "r"(a[0]), "r"(a[1]), "r"(a[2]), "r"(a[3]), "r"(b[0]), "r"(b[1]));
}

__global__ void __launch_bounds__(256, 2)
k_gemm_mma(const float* __restrict__ bihf, const float* __restrict__ bhhf,
           const float* __restrict__ bihb, const float* __restrict__ bhhb,
           const int* __restrict__ lengths) {
    extern __shared__ __align__(16) __nv_bfloat16 smem[];
    __nv_bfloat16* sA = smem;
    __nv_bfloat16* sB = smem + 3 * STAGE_ELEMS;

    int tid = threadIdx.x;
    int wid = tid >> 5;
    int lane = tid & 31;
    int warpM = wid & 3;
    int warpN = wid >> 2;
    int m0 = blockIdx.y * 128;
    int n0g = blockIdx.x * 128;
    int dir = n0g >> 10;
    int n0 = n0g & 1023;

    const __nv_bfloat16* xa = d_xb + (size_t)m0 * KP;
    const __nv_bfloat16* wa = d_wb + (size_t)n0g * KP;

    int v0 = tid * 2;
    int r0i = v0 >> 2, j0 = v0 & 3;
    int v1 = v0 + 1;
    int r1i = v1 >> 2, j1 = v1 & 3;

    uint32_t sA0 = smem_u32(&sA[r0i * APITCH + j0 * 8]);
    uint32_t sA1 = smem_u32(&sA[r1i * APITCH + j1 * 8]);
    uint32_t sB0 = smem_u32(&sB[r0i * APITCH + j0 * 8]);
    uint32_t sB1 = smem_u32(&sB[r1i * APITCH + j1 * 8]);
    const uint32_t stageB = STAGE_ELEMS * 2;

    float acc[2][8][4];
#pragma unroll
    for (int mf = 0; mf < 2; mf++)
#pragma unroll
        for (int nf = 0; nf < 8; nf++)
#pragma unroll
            for (int q = 0; q < 4; q++) acc[mf][nf][q] = 0.f;

#pragma unroll
    for (int s = 0; s < 2; s++) {
        const __nv_bfloat16* xan = xa + s * 32;
        const __nv_bfloat16* wan = wa + s * 32;
        cp_async16(sA0 + s * stageB, xan + (size_t)r0i * KP + j0 * 8);
        cp_async16(sA1 + s * stageB, xan + (size_t)r1i * KP + j1 * 8);
        cp_async16(sB0 + s * stageB, wan + (size_t)r0i * KP + j0 * 8);
        cp_async16(sB1 + s * stageB, wan + (size_t)r1i * KP + j1 * 8);
        CP_COMMIT();
    }
    CP_WAIT(1);
    __syncthreads();

    int aRow = warpM * 32 + (lane & 15);
    int aCol = (lane >> 4) << 3;
    int bRowBase = warpN * 64 + ((lane >> 4) << 3) + (lane & 7);
    int bCol = ((lane >> 3) & 1) << 3;

    for (int c = 0; c < 20; c++) {
        int buf = c % 3;
        if (c + 2 < 20) {
            int nb = (c + 2) % 3;
            const __nv_bfloat16* xan = xa + (c + 2) * 32;
            const __nv_bfloat16* wan = wa + (c + 2) * 32;
            cp_async16(sA0 + nb * stageB, xan + (size_t)r0i * KP + j0 * 8);
            cp_async16(sA1 + nb * stageB, xan + (size_t)r1i * KP + j1 * 8);
            cp_async16(sB0 + nb * stageB, wan + (size_t)r0i * KP + j0 * 8);
            cp_async16(sB1 + nb * stageB, wan + (size_t)r1i * KP + j1 * 8);
            CP_COMMIT();
        }
        const __nv_bfloat16* bufA = sA + buf * STAGE_ELEMS;
        const __nv_bfloat16* bufB = sB + buf * STAGE_ELEMS;
#pragma unroll
        for (int ks = 0; ks < 2; ks++) {
            int kc = ks * 16;
            uint32_t af[2][4];
#pragma unroll
            for (int mf = 0; mf < 2; mf++)
                ldm_x4(af[mf], smem_u32(&bufA[(aRow + mf * 16) * APITCH + kc + aCol]));
            uint32_t bf[4][4];
#pragma unroll
            for (int p = 0; p < 4; p++)
                ldm_x4(bf[p], smem_u32(&bufB[(bRowBase + p * 16) * APITCH + kc + bCol]));
#pragma unroll
            for (int mf = 0; mf < 2; mf++)
#pragma unroll
                for (int nf = 0; nf < 8; nf++)
                    mma16816(acc[mf][nf], af[mf], &bf[nf >> 1][(nf & 1) * 2]);
        }
        if (c + 1 < 20) {
            if (c + 2 < 20) { CP_WAIT(1); } else { CP_WAIT(0); }
            __syncthreads();
        }
    }

    const float* bihp = dir ? bihb : bihf;
    const float* bhhp = dir ? bhhb : bhhf;
    int groupID = lane >> 2;
    int qn = (lane & 3) * 2;
#pragma unroll
    for (int mf = 0; mf < 2; mf++) {
#pragma unroll
        for (int mr = 0; mr < 2; mr++) {
            int m = m0 + warpM * 32 + mf * 16 + groupID + mr * 8;
            int b = m >> 8, t = m & 255;
            int row = t;
            if (dir) {
                int len = lengths[b];
                row = (t < len) ? (len - 1 - t) : t;
            }
            float* outp = d_g + ((size_t)dir * M_ + (size_t)row * B_ + b) * G4_;
#pragma unroll
            for (int nf = 0; nf < 8; nf++) {
                int n = n0 + warpN * 64 + nf * 8 + qn;
                float2 o;
                o.x = acc[mf][nf][mr * 2 + 0] + bihp[n] + bhhp[n];
                o.y = acc[mf][nf][mr * 2 + 1] + bihp[n + 1] + bhhp[n + 1];
                *(float2*)(outp + n) = o;
            }
        }
    }
}

// ------------------------- K3: persistent bidirectional LSTM recurrence -------------------------
// Tensor-core phase-1: warp kc computes gh k-partial over its 32-k chunk for ALL 128
// gate-rows via mma.sync bf16 m16n8k16 (batches padded 8->16; Whh fragments persist
// in registers). R11 flag protocol unchanged.
#define RPITCH 132
__global__ void __launch_bounds__(256, 1)
k_rec(const float* __restrict__ Whh_f, const float* __restrict__ Whh_b,
      const int* __restrict__ lengths) {
    __shared__ float sRed[8 * 8 * RPITCH];   // [kc][batch] pitch 132 (128 rows used)

    int tid = threadIdx.x;
    int bx = blockIdx.x;
    int dir = bx >> 6;
    int r6 = bx & 63;
    int bbt = r6 >> 3;
    int ut = r6 & 7;
    int u0 = ut * 32;
    const float* Whh = dir ? Whh_b : Whh_f;
    const float* gbase = d_g + (size_t)dir * M_ * G4_;
    int grp = dir * 8 + bbt;
    float* hbufGrp = d_hbuf + (size_t)grp * 2 * 2048;
    unsigned fbase = (unsigned)(grp * 8);

    int kc = tid >> 5;     // warp id = k-chunk 0..7
    int lane = tid & 31;
    int g = lane >> 2;     // mma groupID (= batch for A/D)
    int cc = lane & 3;

    int bb2 = tid >> 5;    // phase-2 batch
    int q2 = lane;         // phase-2 unit offset
    int batch2 = bbt * 8 + bb2;
    int len2 = lengths[batch2];

    // ---- persistent B fragments: Whh rows as bf16x2 regs ----
    // nfrag f covers local rows f*8..f*8+7; lane holds row r=f*8+g, k = kc*32 + q*16 + 2cc (+1, +8, +9)
    uint32_t Bf[16][2][2];
#pragma unroll
    for (int f = 0; f < 16; f++) {
        int r = f * 8 + g;
        int grow = (r >> 5) * 256 + u0 + (r & 31);
        const float* wr = Whh + (size_t)grow * 256 + kc * 32;
#pragma unroll
        for (int q = 0; q < 2; q++) {
            int kb = q * 16 + 2 * cc;
            float2 w01 = *(const float2*)(wr + kb);
            float2 w89 = *(const float2*)(wr + kb + 8);
            Bf[f][q][0] = bf16x2_pack(w01.y, w01.x);
            Bf[f][q][1] = bf16x2_pack(w89.y, w89.x);
        }
    }

    float c = 0.f;
    __syncthreads();

    // preload step 0's gates
    float gpre[4];
    {
        const float* gx = gbase + (size_t)batch2 * G4_;
#pragma unroll
        for (int gg = 0; gg < 4; gg++) gpre[gg] = gx[gg * 256 + u0 + q2];
    }

    float* sOut = &sRed[(kc * 8 + g) * RPITCH + 2 * cc];   // + f*8 per frag

    for (int step = 0; step < 256; step++) {
        // next step's gate prefetch
        float gnxt[4];
        if (step + 1 < 256) {
            const float* gx = gbase + ((size_t)(step + 1) * B_ + batch2) * G4_;
#pragma unroll
            for (int gg = 0; gg < 4; gg++) gnxt[gg] = __ldcg(&gx[gg * 256 + u0 + q2]);
        }

        // ---- phase 1 ----
        if (step == 0) {
#pragma unroll
            for (int f = 0; f < 16; f++)
                *(float2*)(sOut + f * 8) = make_float2(0.f, 0.f);
        } else {
            if (lane == 0) {
                unsigned v;
                do {
                    asm volatile("ld.acquire.gpu.global.u32 %0, [%1];"
                                 : "=r"(v) : "l"(&g_flag[fbase + kc]) : "memory");
                } while (v < (unsigned)step);
            }
            __syncwarp();
            int rb = (step - 1) & 1;
            const float* hsrc = hbufGrp + rb * 2048 + kc * 256;   // [unit*8 + batch]
            uint32_t Af[2][2];
#pragma unroll
            for (int q = 0; q < 2; q++) {
                int ub = q * 16 + 2 * cc;
                float h0 = __ldcg(hsrc + ub * 8 + g);
                float h1 = __ldcg(hsrc + (ub + 1) * 8 + g);
                float h2 = __ldcg(hsrc + (ub + 8) * 8 + g);
                float h3 = __ldcg(hsrc + (ub + 9) * 8 + g);
                Af[q][0] = bf16x2_pack(h1, h0);
                Af[q][1] = bf16x2_pack(h3, h2);
            }
            float a0[16], a1[16];
            float j0, j1;
#pragma unroll
            for (int f = 0; f < 16; f++) {
                // q=0: C = {0,0,junk,junk}
                asm volatile(
                    "mma.sync.aligned.m16n8k16.row.col.f32.bf16.bf16.f32 "
                    "{%0,%1,%2,%3}, {%4,%5,%6,%7}, {%8,%9}, {%10,%11,%2,%3};"
                    : "=f"(a0[f]), "=f"(a1[f]), "+f"(j0), "+f"(j1)
                    : "r"(Af[0][0]), "r"(0u), "r"(Af[0][1]), "r"(0u),
                      "r"(Bf[f][0][0]), "r"(Bf[f][0][1]), "f"(0.f), "f"(0.f));
                // q=1: accumulate
                asm volatile(
                    "mma.sync.aligned.m16n8k16.row.col.f32.bf16.bf16.f32 "
                    "{%0,%1,%2,%3}, {%4,%5,%6,%7}, {%8,%9}, {%0,%1,%2,%3};"
                    : "+f"(a0[f]), "+f"(a1[f]), "+f"(j0), "+f"(j1)
                    : "r"(Af[1][0]), "r"(0u), "r"(Af[1][1]), "r"(0u),
                      "r"(Bf[f][1][0]), "r"(Bf[f][1][1]));
            }
#pragma unroll
            for (int f = 0; f < 16; f++)
                *(float2*)(sOut + f * 8) = make_float2(a0[f], a1[f]);
        }
        __syncthreads();

        // ---- phase 2: gates, cell update ----
        float gate[4];
#pragma unroll
        for (int gg = 0; gg < 4; gg++) {
            float s = gpre[gg];
#pragma unroll
            for (int kcc = 0; kcc < 8; kcc++)
                s += sRed[(kcc * 8 + bb2) * RPITCH + gg * 32 + q2];
            gate[gg] = s;
        }
        float i_ = sigm(gate[0]);
        float f_ = sigm(gate[1]);
        float gg_ = tanh_ap(gate[2]);
        float o_ = sigm(gate[3]);
        c = f_ * c + i_ * gg_;
        float h = o_ * tanh_ap(c);

        int wbuf = step & 1;
        __stcg(&hbufGrp[wbuf * 2048 + (u0 + q2) * 8 + bb2], h);

        __syncthreads();
        if (tid == 0) {
            asm volatile("red.release.gpu.global.add.u32 [%0], %1;"
                         :: "l"(&g_flag[fbase + ut]), "r"(1u) : "memory");
        }

        int tout = dir ? ((step < len2) ? (len2 - 1 - step) : step) : step;
        d_h[((size_t)batch2 * T_ + tout) * 512 + dir * 256 + u0 + q2] = h;

#pragma unroll
        for (int gg = 0; gg < 4; gg++) gpre[gg] = gnxt[gg];
    }
}

// ------------------------- K4: emissions = h . Wlin^T + blin -------------------------
__global__ void __launch_bounds__(128)
k_emis(const float* __restrict__ Wlin, const float* __restrict__ blin) {
    __shared__ float sW[15 * 516];
    __shared__ float sh[8 * 512];
    int tid = threadIdx.x;
    for (int i = tid; i < 15 * 512; i += 128) {
        int l = i >> 9, k = i & 511;
        sW[l * 516 + k] = Wlin[i];
    }
    int m0 = blockIdx.x * 8;
    const float4* hsrc = (const float4*)(d_h + (size_t)m0 * 512);
    for (int i = tid; i < 8 * 512 / 4; i += 128)
        ((float4*)sh)[i] = hsrc[i];
    __syncthreads();

    int r = tid >> 4, l = tid & 15;
    if (l < 15) {
        float s = blin[l];
        const float* hw = sh + r * 512;
        const float* ww = sW + l * 516;
#pragma unroll 8
        for (int k = 0; k < 512; k += 4) {
            float4 hv = *(const float4*)(hw + k);
            float4 wv = *(const float4*)(ww + k);
            s += hv.x * wv.x + hv.y * wv.y + hv.z * wv.z + hv.w * wv.w;
        }
        d_emis[(size_t)(m0 + r) * L_ + l] = s;
    }
}

// ------------------------- K5: CRF NLL per sequence -------------------------
__global__ void k_crf(const int* __restrict__ lengths, const int* __restrict__ labels,
                      const float* __restrict__ start_t, const float* __restrict__ end_t,
                      const float* __restrict__ trans) {
    int b = blockIdx.x;
    int lane = threadIdx.x;
    int len = lengths[b];
    const float* em = d_emis + (size_t)b * T_ * L_;
    int j = (lane < L_) ? lane : 0;

    float tr[L_];
#pragma unroll
    for (int i = 0; i < L_; i++) tr[i] = trans[i * L_ + j];

    float alpha = start_t[j] + em[j];
    for (int t = 1; t < T_; t++) {
        float v[L_], mx = -1e30f;
#pragma unroll
        for (int i = 0; i < L_; i++) {
            float av = __shfl_sync(0xffffffffu, alpha, i);
            v[i] = av + tr[i];
            mx = fmaxf(mx, v[i]);
        }
        float s = 0.f;
#pragma unroll
        for (int i = 0; i < L_; i++) s += __expf(v[i] - mx);
        float nxt = mx + __logf(s) + em[t * L_ + j];
        if (t < len) alpha = nxt;
    }
    float vv = (lane < L_) ? (alpha + end_t[lane]) : -1e30f;
    float mx = vv;
#pragma unroll
    for (int o = 16; o; o >>= 1) mx = fmaxf(mx, __shfl_xor_sync(0xffffffffu, mx, o));
    float se = (lane < L_) ? __expf(vv - mx) : 0.f;
#pragma unroll
    for (int o = 16; o; o >>= 1) se += __shfl_xor_sync(0xffffffffu, se, o);
    float den = mx + __logf(se);

    const int* tg = labels + b * T_;
    float em_s = 0.f, tr_s = 0.f;
    for (int t = lane; t < T_; t += 32) {
        if (t < len) {
            em_s += em[t * L_ + tg[t]];
            if (t >= 1) tr_s += trans[tg[t - 1] * L_ + tg[t]];
        }
    }
#pragma unroll
    for (int o = 16; o; o >>= 1) {
        em_s += __shfl_xor_sync(0xffffffffu, em_s, o);
        tr_s += __shfl_xor_sync(0xffffffffu, tr_s, o);
    }
    if (lane == 0) {
        float num = start_t[tg[0]] + em_s + tr_s + end_t[tg[len - 1]];
        d_partial[b] = num - den;
    }
}

// ------------------------- K6: deterministic final sum -------------------------
__global__ void k_final(float* __restrict__ out) {
    float s = 0.f;
#pragma unroll
    for (int b = 0; b < B_; b++) s += d_partial[b];
    out[0] = -s;
}

// ------------------------- launch -------------------------
extern "C" void kernel_launch(void* const* d_in, const int* in_sizes, int n_in,
                              void* d_out, int out_size) {
    const int*   input_ids    = (const int*)d_in[0];
    const int*   lengths      = (const int*)d_in[1];
    const int*   softword_ids = (const int*)d_in[2];
    const int*   label_ids    = (const int*)d_in[3];
    const float* emb          = (const float*)d_in[4];
    const float* soft_emb     = (const float*)d_in[5];
    const float* Wih_f        = (const float*)d_in[6];
    const float* Whh_f        = (const float*)d_in[7];
    const float* bih_f        = (const float*)d_in[8];
    const float* bhh_f        = (const float*)d_in[9];
    const float* Wih_b        = (const float*)d_in[10];
    const float* Whh_b        = (const float*)d_in[11];
    const float* bih_b        = (const float*)d_in[12];
    const float* bhh_b        = (const float*)d_in[13];
    const float* Wlin         = (const float*)d_in[14];
    const float* blin         = (const float*)d_in[15];
    const float* start_t      = (const float*)d_in[16];
    const float* end_t        = (const float*)d_in[17];
    const float* trans        = (const float*)d_in[18];
    float* out = (float*)d_out;

    cudaFuncSetAttribute(k_gemm_mma, cudaFuncAttributeMaxDynamicSharedMemorySize, GSMEM_BYTES);

    k_init<<<1, 128>>>();
    k_embed<<<M_, 320>>>(input_ids, softword_ids, emb, soft_emb);
    k_wconv<<<(2048 * KP + 511) / 512, 512>>>(Wih_f, Wih_b);
    dim3 g2(16, 128);
    k_gemm_mma<<<g2, 256, GSMEM_BYTES>>>(bih_f, bhh_f, bih_b, bhh_b, lengths);
    k_rec<<<128, 256>>>(Whh_f, Whh_b, lengths);
    k_emis<<<2048, 128>>>(Wlin, blin);
    k_crf<<<B_, 32>>>(lengths, label_ids, start_t, end_t, trans);
    k_final<<<1, 1>>>(out);
}

// round 13
// speedup vs baseline: 1.1945x; 1.1945x over previous
#include <cuda_runtime.h>
#include <cuda_bf16.h>
#include <cstdint>

// Problem constants
#define B_ 64
#define T_ 256
#define H_ 256
#define G4_ 1024      // 4*H
#define KRAW 600      // 2*E
#define KP 640        // padded K (20 chunks of 32)
#define L_ 15
#define M_ (B_*T_)    // 16384

// ------------------------- device scratch (no allocations) -------------------------
__device__ __align__(16) __nv_bfloat16 d_xb[(size_t)M_ * KP];    // [16384, 640] bf16
__device__ __align__(16) __nv_bfloat16 d_wb[(size_t)2048 * KP];  // [2048, 640] bf16
__device__ float d_g[(size_t)2 * M_ * G4_];               // [dir][t(or s)][b][1024]
__device__ float d_h[(size_t)M_ * 2 * H_];                // [b][t][512] = [h_f | h_b]
__device__ float d_emis[(size_t)M_ * L_];                 // [b][t][15]
__device__ __align__(16) unsigned d_hbuf[2 * 8 * 2 * 2048]; // [dir][bbt][buf][unit*8+batch] tagged bf16
__device__ float d_partial[B_];

// ------------------------- helpers -------------------------
__device__ __forceinline__ float sigm(float x) {
    float e = __expf(-x);
    return __fdividef(1.0f, 1.0f + e);
}
__device__ __forceinline__ float tanh_ap(float x) {
    float y;
    asm("tanh.approx.f32 %0, %1;" : "=f"(y) : "f"(x));
    return y;
}
__device__ __forceinline__ float sel4(float4 v, int j) {
    float x = v.x;
    x = (j == 1) ? v.y : x;
    x = (j == 2) ? v.z : x;
    x = (j == 3) ? v.w : x;
    return x;
}
__device__ __forceinline__ uint32_t smem_u32(const void* p) {
    uint32_t a;
    asm("{ .reg .u64 t; cvta.to.shared.u64 t, %1; cvt.u32.u64 %0, t; }" : "=r"(a) : "l"(p));
    return a;
}
// packed f32x2 helpers
__device__ __forceinline__ unsigned long long pack2(float a, float b) {
    unsigned long long r;
    asm("mov.b64 %0, {%1, %2};" : "=l"(r) : "f"(a), "f"(b));
    return r;
}
__device__ __forceinline__ void ffma2(unsigned long long& d, unsigned long long a,
                                      unsigned long long b) {
    asm("fma.rn.f32x2 %0, %1, %2, %0;" : "+l"(d) : "l"(a), "l"(b));
}
__device__ __forceinline__ float2 unpack2(unsigned long long v) {
    float2 r;
    asm("mov.b64 {%0, %1}, %2;" : "=f"(r.x), "=f"(r.y) : "l"(v));
    return r;
}
// cp.async helpers (sm_80 base ISA)
__device__ __forceinline__ void cp_async16(uint32_t dst, const void* src) {
    asm volatile("cp.async.cg.shared.global [%0], [%1], 16;" :: "r"(dst), "l"(src));
}
#define CP_COMMIT() asm volatile("cp.async.commit_group;" ::: "memory")
#define CP_WAIT(n)  asm volatile("cp.async.wait_group %0;" :: "n"(n) : "memory")

// ------------------------- K0: reset tagged h buffer (per replay) -------------------------
__global__ void k_init() {
    int idx = blockIdx.x * blockDim.x + threadIdx.x;
    if (idx < 2 * 8 * 2 * 2048) d_hbuf[idx] = 0u;
}

// ------------------------- K1: embedding gather + concat + bf16 + pad -------------------------
__global__ void k_embed(const int* __restrict__ ids, const int* __restrict__ sids,
                        const float* __restrict__ emb, const float* __restrict__ semb) {
    int m = blockIdx.x;
    int c = threadIdx.x;
    __nv_bfloat16* xp = d_xb + (size_t)m * KP;
    if (c < 300) {
        int id = ids[m];
        int sid = sids[m];
        xp[c]       = __float2bfloat16_rn(emb[(size_t)id * 300 + c]);
        xp[300 + c] = __float2bfloat16_rn(semb[(size_t)sid * 300 + c]);
    } else {
        int z = c - 300;
        xp[600 + z] = __float2bfloat16_rn(0.f);
        xp[620 + z] = __float2bfloat16_rn(0.f);
    }
}

// ------------------------- K1b: weight conversion to bf16 (padded) -------------------------
__global__ void k_wconv(const float* __restrict__ Wf, const float* __restrict__ Wb) {
    int idx = blockIdx.x * blockDim.x + threadIdx.x;
    if (idx >= 2048 * KP) return;
    int row = idx / KP, k = idx - row * KP;
    float v = 0.f;
    if (k < KRAW) v = (row < 1024) ? Wf[row * KRAW + k] : Wb[(row - 1024) * KRAW + k];
    d_wb[idx] = __float2bfloat16_rn(v);
}

// ------------------------- K2: mma.sync bf16 GEMM, cp.async 3-stage (R11, proven 181us) -------------------------
#define APITCH 40
#define STAGE_ELEMS (128 * APITCH)
#define GSMEM_BYTES (3 * 2 * STAGE_ELEMS * 2)

__device__ __forceinline__ void ldm_x4(uint32_t* r, uint32_t addr) {
    asm volatile("ldmatrix.sync.aligned.m8n8.x4.shared.b16 {%0,%1,%2,%3}, [%4];"
                 : "=r"(r[0]), "=r"(r[1]), "=r"(r[2]), "=r"(r[3]) : "r"(addr));
}
__device__ __forceinline__ void mma16816(float* c, const uint32_t* a, const uint32_t* b) {
    asm volatile(
        "mma.sync.aligned.m16n8k16.row.col.f32.bf16.bf16.f32 "
        "{%0,%1,%2,%3}, {%4,%5,%6,%7}, {%8,%9}, {%0,%1,%2,%3};"
        : "+f"(c[0]), "+f"(c[1]), "+f"(c[2]), "+f"(c[3])
        : "r"(a[0]), "r"(a[1]), "r"(a[2]), "r"(a[3]), "r"(b[0]), "r"(b[1]));
}

__global__ void __launch_bounds__(256, 2)
k_gemm_mma(const float* __restrict__ bihf, const float* __restrict__ bhhf,
           const float* __restrict__ bihb, const float* __restrict__ bhhb,
           const int* __restrict__ lengths) {
    extern __shared__ __align__(16) __nv_bfloat16 smem[];
    __nv_bfloat16* sA = smem;
    __nv_bfloat16* sB = smem + 3 * STAGE_ELEMS;

    int tid = threadIdx.x;
    int wid = tid >> 5;
    int lane = tid & 31;
    int warpM = wid & 3;
    int warpN = wid >> 2;
    int m0 = blockIdx.y * 128;
    int n0g = blockIdx.x * 128;
    int dir = n0g >> 10;
    int n0 = n0g & 1023;

    const __nv_bfloat16* xa = d_xb + (size_t)m0 * KP;
    const __nv_bfloat16* wa = d_wb + (size_t)n0g * KP;

    int v0 = tid * 2;
    int r0i = v0 >> 2, j0 = v0 & 3;
    int v1 = v0 + 1;
    int r1i = v1 >> 2, j1 = v1 & 3;

    uint32_t sA0 = smem_u32(&sA[r0i * APITCH + j0 * 8]);
    uint32_t sA1 = smem_u32(&sA[r1i * APITCH + j1 * 8]);
    uint32_t sB0 = smem_u32(&sB[r0i * APITCH + j0 * 8]);
    uint32_t sB1 = smem_u32(&sB[r1i * APITCH + j1 * 8]);
    const uint32_t stageB = STAGE_ELEMS * 2;

    float acc[2][8][4];
#pragma unroll
    for (int mf = 0; mf < 2; mf++)
#pragma unroll
        for (int nf = 0; nf < 8; nf++)
#pragma unroll
            for (int q = 0; q < 4; q++) acc[mf][nf][q] = 0.f;

#pragma unroll
    for (int s = 0; s < 2; s++) {
        const __nv_bfloat16* xan = xa + s * 32;
        const __nv_bfloat16* wan = wa + s * 32;
        cp_async16(sA0 + s * stageB, xan + (size_t)r0i * KP + j0 * 8);
        cp_async16(sA1 + s * stageB, xan + (size_t)r1i * KP + j1 * 8);
        cp_async16(sB0 + s * stageB, wan + (size_t)r0i * KP + j0 * 8);
        cp_async16(sB1 + s * stageB, wan + (size_t)r1i * KP + j1 * 8);
        CP_COMMIT();
    }
    CP_WAIT(1);
    __syncthreads();

    int aRow = warpM * 32 + (lane & 15);
    int aCol = (lane >> 4) << 3;
    int bRowBase = warpN * 64 + ((lane >> 4) << 3) + (lane & 7);
    int bCol = ((lane >> 3) & 1) << 3;

    for (int c = 0; c < 20; c++) {
        int buf = c % 3;
        if (c + 2 < 20) {
            int nb = (c + 2) % 3;
            const __nv_bfloat16* xan = xa + (c + 2) * 32;
            const __nv_bfloat16* wan = wa + (c + 2) * 32;
            cp_async16(sA0 + nb * stageB, xan + (size_t)r0i * KP + j0 * 8);
            cp_async16(sA1 + nb * stageB, xan + (size_t)r1i * KP + j1 * 8);
            cp_async16(sB0 + nb * stageB, wan + (size_t)r0i * KP + j0 * 8);
            cp_async16(sB1 + nb * stageB, wan + (size_t)r1i * KP + j1 * 8);
            CP_COMMIT();
        }
        const __nv_bfloat16* bufA = sA + buf * STAGE_ELEMS;
        const __nv_bfloat16* bufB = sB + buf * STAGE_ELEMS;
#pragma unroll
        for (int ks = 0; ks < 2; ks++) {
            int kc = ks * 16;
            uint32_t af[2][4];
#pragma unroll
            for (int mf = 0; mf < 2; mf++)
                ldm_x4(af[mf], smem_u32(&bufA[(aRow + mf * 16) * APITCH + kc + aCol]));
            uint32_t bf[4][4];
#pragma unroll
            for (int p = 0; p < 4; p++)
                ldm_x4(bf[p], smem_u32(&bufB[(bRowBase + p * 16) * APITCH + kc + bCol]));
#pragma unroll
            for (int mf = 0; mf < 2; mf++)
#pragma unroll
                for (int nf = 0; nf < 8; nf++)
                    mma16816(acc[mf][nf], af[mf], &bf[nf >> 1][(nf & 1) * 2]);
        }
        if (c + 1 < 20) {
            if (c + 2 < 20) { CP_WAIT(1); } else { CP_WAIT(0); }
            __syncthreads();
        }
    }

    const float* bihp = dir ? bihb : bihf;
    const float* bhhp = dir ? bhhb : bhhf;
    int groupID = lane >> 2;
    int qn = (lane & 3) * 2;
#pragma unroll
    for (int mf = 0; mf < 2; mf++) {
#pragma unroll
        for (int mr = 0; mr < 2; mr++) {
            int m = m0 + warpM * 32 + mf * 16 + groupID + mr * 8;
            int b = m >> 8, t = m & 255;
            int row = t;
            if (dir) {
                int len = lengths[b];
                row = (t < len) ? (len - 1 - t) : t;
            }
            float* outp = d_g + ((size_t)dir * M_ + (size_t)row * B_ + b) * G4_;
#pragma unroll
            for (int nf = 0; nf < 8; nf++) {
                int n = n0 + warpN * 64 + nf * 8 + qn;
                float2 o;
                o.x = acc[mf][nf][mr * 2 + 0] + bihp[n] + bhhp[n];
                o.y = acc[mf][nf][mr * 2 + 1] + bihp[n + 1] + bhhp[n + 1];
                *(float2*)(outp + n) = o;
            }
        }
    }
}

// ------------------------- K3: persistent bidirectional LSTM recurrence -------------------------
// R11 FFMA2 compute; exchange via SELF-VALIDATING tagged words:
//   word = (bf16(h) << 16) | (step+1).  Consumer polls its data chunk directly
//   (one L2 round trip, no flags, no fences); unpack = AND mask.
__global__ void __launch_bounds__(256, 1)
k_rec(const float* __restrict__ Whh_f, const float* __restrict__ Whh_b,
      const int* __restrict__ lengths) {
    __shared__ __align__(16) float sH[2048];   // [unit*8 + batch]; warp-private 256-float chunks
    __shared__ float4 sRed[8 * 8 * 32];        // [kc][bb][rowgroup] partial gate sums

    int tid = threadIdx.x;
    int bx = blockIdx.x;
    int dir = bx >> 6;
    int r6 = bx & 63;
    int bbt = r6 >> 3;
    int ut = r6 & 7;
    int u0 = ut * 32;
    const float* Whh = dir ? Whh_b : Whh_f;
    const float* gbase = d_g + (size_t)dir * M_ * G4_;
    int grp = dir * 8 + bbt;
    unsigned* hbufGrp = d_hbuf + (size_t)grp * 2 * 2048;

    int kc = tid >> 5;   // 0..7 (uniform per warp)
    int rg = tid & 31;
    int lane = rg;

    int bb2 = tid >> 5;  // 0..7
    int q2 = tid & 31;
    int batch2 = bbt * 8 + bb2;
    int len2 = lengths[batch2];
    int jsel = q2 & 3;

    // Whh slice in registers (R11 mapping)
    float W[4][32];
#pragma unroll
    for (int j = 0; j < 4; j++) {
        int r = rg * 4 + j;
        int grow = (r >> 5) * 256 + u0 + (r & 31);
        const float* wp = Whh + (size_t)grow * 256 + kc * 32;
#pragma unroll
        for (int kk = 0; kk < 32; kk += 4) {
            float4 v = *(const float4*)(wp + kk);
            W[j][kk] = v.x; W[j][kk + 1] = v.y; W[j][kk + 2] = v.z; W[j][kk + 3] = v.w;
        }
    }

    for (int i = tid; i < 2048; i += 256) sH[i] = 0.f;

    float c = 0.f;
    __syncthreads();

    // preload step 0's gates
    float gpre[4];
    {
        const float* gx = gbase + (size_t)batch2 * G4_;
#pragma unroll
        for (int g = 0; g < 4; g++) gpre[g] = gx[g * 256 + u0 + q2];
    }

    for (int step = 0; step < 256; step++) {
        // next step's gate prefetch (full-step latency cover)
        float gnxt[4];
        if (step + 1 < 256) {
            const float* gx = gbase + ((size_t)(step + 1) * B_ + batch2) * G4_;
#pragma unroll
            for (int g = 0; g < 4; g++) gnxt[g] = __ldcg(&gx[g * 256 + u0 + q2]);
        }

        // ---- fetch this warp's h chunk: poll directly on tagged data ----
        if (step > 0) {
            int rb = (step - 1) & 1;
            const unsigned* src = hbufGrp + rb * 2048 + kc * 256 + lane * 8;
            unsigned expect = (unsigned)step;
            unsigned w0, w1, w2, w3, w4, w5, w6, w7;
            int tries = 0;
            for (;;) {
                asm volatile("ld.global.cg.v4.u32 {%0,%1,%2,%3}, [%4];"
                             : "=r"(w0), "=r"(w1), "=r"(w2), "=r"(w3)
                             : "l"(src) : "memory");
                asm volatile("ld.global.cg.v4.u32 {%0,%1,%2,%3}, [%4];"
                             : "=r"(w4), "=r"(w5), "=r"(w6), "=r"(w7)
                             : "l"(src + 4) : "memory");
                bool ok = ((w0 & 0xFFFFu) == expect) & ((w1 & 0xFFFFu) == expect)
                        & ((w2 & 0xFFFFu) == expect) & ((w3 & 0xFFFFu) == expect)
                        & ((w4 & 0xFFFFu) == expect) & ((w5 & 0xFFFFu) == expect)
                        & ((w6 & 0xFFFFu) == expect) & ((w7 & 0xFFFFu) == expect);
                if (__all_sync(0xffffffffu, ok)) break;
                if (++tries > 2) __nanosleep(40);
            }
            float4 fa, fb;
            fa.x = __uint_as_float(w0 & 0xFFFF0000u);
            fa.y = __uint_as_float(w1 & 0xFFFF0000u);
            fa.z = __uint_as_float(w2 & 0xFFFF0000u);
            fa.w = __uint_as_float(w3 & 0xFFFF0000u);
            fb.x = __uint_as_float(w4 & 0xFFFF0000u);
            fb.y = __uint_as_float(w5 & 0xFFFF0000u);
            fb.z = __uint_as_float(w6 & 0xFFFF0000u);
            fb.w = __uint_as_float(w7 & 0xFFFF0000u);
            *(float4*)&sH[kc * 256 + lane * 8]     = fa;
            *(float4*)&sH[kc * 256 + lane * 8 + 4] = fb;
            __syncwarp();
        }
        __syncthreads();   // sRed WAR: prev phase-2 reads done before new writes

        // ---- phase 1: packed f32x2 partials (R11, proven) ----
        unsigned long long acc2[4][4];
#pragma unroll
        for (int p = 0; p < 4; p++)
#pragma unroll
            for (int j = 0; j < 4; j++) acc2[p][j] = pack2(0.f, 0.f);

        const ulonglong2* hp2 = (const ulonglong2*)&sH[kc * 256];
#pragma unroll
        for (int kk = 0; kk < 32; kk++) {
            ulonglong2 ha = hp2[kk * 2 + 0];
            ulonglong2 hb = hp2[kk * 2 + 1];
            unsigned long long h0 = ha.x, h1 = ha.y, h2 = hb.x, h3 = hb.y;
#pragma unroll
            for (int j = 0; j < 4; j++) {
                unsigned long long wv = pack2(W[j][kk], W[j][kk]);
                ffma2(acc2[0][j], h0, wv);
                ffma2(acc2[1][j], h1, wv);
                ffma2(acc2[2][j], h2, wv);
                ffma2(acc2[3][j], h3, wv);
            }
        }
#pragma unroll
        for (int p = 0; p < 4; p++) {
            float4 lo, hi;
            float2 u0v = unpack2(acc2[p][0]);
            float2 u1v = unpack2(acc2[p][1]);
            float2 u2v = unpack2(acc2[p][2]);
            float2 u3v = unpack2(acc2[p][3]);
            lo.x = u0v.x; lo.y = u1v.x; lo.z = u2v.x; lo.w = u3v.x;
            hi.x = u0v.y; hi.y = u1v.y; hi.z = u2v.y; hi.w = u3v.y;
            sRed[(kc * 8 + p * 2 + 0) * 32 + rg] = lo;
            sRed[(kc * 8 + p * 2 + 1) * 32 + rg] = hi;
        }
        __syncthreads();

        // ---- phase 2: gates, cell update ----
        float gate[4];
#pragma unroll
        for (int g = 0; g < 4; g++) {
            int rgl = g * 8 + (q2 >> 2);
            float s = gpre[g];
#pragma unroll
            for (int kcc = 0; kcc < 8; kcc++)
                s += sel4(sRed[(kcc * 8 + bb2) * 32 + rgl], jsel);
            gate[g] = s;
        }
        float i_ = sigm(gate[0]);
        float f_ = sigm(gate[1]);
        float gg = tanh_ap(gate[2]);
        float o_ = sigm(gate[3]);
        c = f_ * c + i_ * gg;
        float h = o_ * tanh_ap(c);

        // ---- publish tagged word ASAP (no fence needed: word self-validates) ----
        int wbuf = step & 1;
        __nv_bfloat16 hb16 = __float2bfloat16_rn(h);
        unsigned wword = ((unsigned)*(unsigned short*)&hb16 << 16) | (unsigned)(step + 1);
        __stcg(&hbufGrp[wbuf * 2048 + (u0 + q2) * 8 + bb2], wword);

        // d_h store off the critical path
        int tout = dir ? ((step < len2) ? (len2 - 1 - step) : step) : step;
        d_h[((size_t)batch2 * T_ + tout) * 512 + dir * 256 + u0 + q2] = h;

#pragma unroll
        for (int g = 0; g < 4; g++) gpre[g] = gnxt[g];
    }
}

// ------------------------- K4: emissions = h . Wlin^T + blin -------------------------
__global__ void __launch_bounds__(128)
k_emis(const float* __restrict__ Wlin, const float* __restrict__ blin) {
    __shared__ float sW[15 * 516];
    __shared__ float sh[8 * 512];
    int tid = threadIdx.x;
    for (int i = tid; i < 15 * 512; i += 128) {
        int l = i >> 9, k = i & 511;
        sW[l * 516 + k] = Wlin[i];
    }
    int m0 = blockIdx.x * 8;
    const float4* hsrc = (const float4*)(d_h + (size_t)m0 * 512);
    for (int i = tid; i < 8 * 512 / 4; i += 128)
        ((float4*)sh)[i] = hsrc[i];
    __syncthreads();

    int r = tid >> 4, l = tid & 15;
    if (l < 15) {
        float s = blin[l];
        const float* hw = sh + r * 512;
        const float* ww = sW + l * 516;
#pragma unroll 8
        for (int k = 0; k < 512; k += 4) {
            float4 hv = *(const float4*)(hw + k);
            float4 wv = *(const float4*)(ww + k);
            s += hv.x * wv.x + hv.y * wv.y + hv.z * wv.z + hv.w * wv.w;
        }
        d_emis[(size_t)(m0 + r) * L_ + l] = s;
    }
}

// ------------------------- K5: CRF NLL per sequence -------------------------
__global__ void k_crf(const int* __restrict__ lengths, const int* __restrict__ labels,
                      const float* __restrict__ start_t, const float* __restrict__ end_t,
                      const float* __restrict__ trans) {
    int b = blockIdx.x;
    int lane = threadIdx.x;
    int len = lengths[b];
    const float* em = d_emis + (size_t)b * T_ * L_;
    int j = (lane < L_) ? lane : 0;

    float tr[L_];
#pragma unroll
    for (int i = 0; i < L_; i++) tr[i] = trans[i * L_ + j];

    float alpha = start_t[j] + em[j];
    for (int t = 1; t < T_; t++) {
        float v[L_], mx = -1e30f;
#pragma unroll
        for (int i = 0; i < L_; i++) {
            float av = __shfl_sync(0xffffffffu, alpha, i);
            v[i] = av + tr[i];
            mx = fmaxf(mx, v[i]);
        }
        float s = 0.f;
#pragma unroll
        for (int i = 0; i < L_; i++) s += __expf(v[i] - mx);
        float nxt = mx + __logf(s) + em[t * L_ + j];
        if (t < len) alpha = nxt;
    }
    float vv = (lane < L_) ? (alpha + end_t[lane]) : -1e30f;
    float mx = vv;
#pragma unroll
    for (int o = 16; o; o >>= 1) mx = fmaxf(mx, __shfl_xor_sync(0xffffffffu, mx, o));
    float se = (lane < L_) ? __expf(vv - mx) : 0.f;
#pragma unroll
    for (int o = 16; o; o >>= 1) se += __shfl_xor_sync(0xffffffffu, se, o);
    float den = mx + __logf(se);

    const int* tg = labels + b * T_;
    float em_s = 0.f, tr_s = 0.f;
    for (int t = lane; t < T_; t += 32) {
        if (t < len) {
            em_s += em[t * L_ + tg[t]];
            if (t >= 1) tr_s += trans[tg[t - 1] * L_ + tg[t]];
        }
    }
#pragma unroll
    for (int o = 16; o; o >>= 1) {
        em_s += __shfl_xor_sync(0xffffffffu, em_s, o);
        tr_s += __shfl_xor_sync(0xffffffffu, tr_s, o);
    }
    if (lane == 0) {
        float num = start_t[tg[0]] + em_s + tr_s + end_t[tg[len - 1]];
        d_partial[b] = num - den;
    }
}

// ------------------------- K6: deterministic final sum -------------------------
__global__ void k_final(float* __restrict__ out) {
    float s = 0.f;
#pragma unroll
    for (int b = 0; b < B_; b++) s += d_partial[b];
    out[0] = -s;
}

// ------------------------- launch -------------------------
extern "C" void kernel_launch(void* const* d_in, const int* in_sizes, int n_in,
                              void* d_out, int out_size) {
    const int*   input_ids    = (const int*)d_in[0];
    const int*   lengths      = (const int*)d_in[1];
    const int*   softword_ids = (const int*)d_in[2];
    const int*   label_ids    = (const int*)d_in[3];
    const float* emb          = (const float*)d_in[4];
    const float* soft_emb     = (const float*)d_in[5];
    const float* Wih_f        = (const float*)d_in[6];
    const float* Whh_f        = (const float*)d_in[7];
    const float* bih_f        = (const float*)d_in[8];
    const float* bhh_f        = (const float*)d_in[9];
    const float* Wih_b        = (const float*)d_in[10];
    const float* Whh_b        = (const float*)d_in[11];
    const float* bih_b        = (const float*)d_in[12];
    const float* bhh_b        = (const float*)d_in[13];
    const float* Wlin         = (const float*)d_in[14];
    const float* blin         = (const float*)d_in[15];
    const float* start_t      = (const float*)d_in[16];
    const float* end_t        = (const float*)d_in[17];
    const float* trans        = (const float*)d_in[18];
    float* out = (float*)d_out;

    cudaFuncSetAttribute(k_gemm_mma, cudaFuncAttributeMaxDynamicSharedMemorySize, GSMEM_BYTES);

    k_init<<<64, 1024>>>();
    k_embed<<<M_, 320>>>(input_ids, softword_ids, emb, soft_emb);
    k_wconv<<<(2048 * KP + 511) / 512, 512>>>(Wih_f, Wih_b);
    dim3 g2(16, 128);
    k_gemm_mma<<<g2, 256, GSMEM_BYTES>>>(bih_f, bhh_f, bih_b, bhh_b, lengths);
    k_rec<<<128, 256>>>(Whh_f, Whh_b, lengths);
    k_emis<<<2048, 128>>>(Wlin, blin);
    k_crf<<<B_, 32>>>(lengths, label_ids, start_t, end_t, trans);
    k_final<<<1, 1>>>(out);
}

// round 14
// speedup vs baseline: 1.6198x; 1.3560x over previous
#include <cuda_runtime.h>
#include <cuda_bf16.h>
#include <cstdint>

// Problem constants
#define B_ 64
#define T_ 256
#define H_ 256
#define G4_ 1024      // 4*H
#define KRAW 600      // 2*E
#define KP 640        // padded K (20 chunks of 32)
#define L_ 15
#define M_ (B_*T_)    // 16384

// ------------------------- device scratch (no allocations) -------------------------
__device__ __align__(16) __nv_bfloat16 d_xb[(size_t)M_ * KP];    // [16384, 640] bf16
__device__ __align__(16) __nv_bfloat16 d_wb[(size_t)2048 * KP];  // [2048, 640] bf16
__device__ float d_g[(size_t)2 * M_ * G4_];               // [dir][t(or s)][b][1024]
__device__ float d_h[(size_t)M_ * 2 * H_];                // [b][t][512] = [h_f | h_b]
__device__ float d_emis[(size_t)M_ * L_];                 // [b][t][15]
__device__ __align__(16) unsigned d_hbuf[2 * 8 * 2 * 2048]; // [dir][bbt][buf][unit*8+batch] tagged bf16
__device__ float d_partial[B_];

// ------------------------- helpers -------------------------
__device__ __forceinline__ float sigm(float x) {
    float e = __expf(-x);
    return __fdividef(1.0f, 1.0f + e);
}
__device__ __forceinline__ float tanh_ap(float x) {
    float y;
    asm("tanh.approx.f32 %0, %1;" : "=f"(y) : "f"(x));
    return y;
}
__device__ __forceinline__ uint32_t smem_u32(const void* p) {
    uint32_t a;
    asm("{ .reg .u64 t; cvta.to.shared.u64 t, %1; cvt.u32.u64 %0, t; }" : "=r"(a) : "l"(p));
    return a;
}
// pack two f32 into bf16x2 (lo = first/lower-k element)
__device__ __forceinline__ uint32_t bf16x2_pack(float hi, float lo) {
    uint32_t r;
    asm("cvt.rn.bf16x2.f32 %0, %1, %2;" : "=r"(r) : "f"(hi), "f"(lo));
    return r;
}
// cp.async helpers (sm_80 base ISA)
__device__ __forceinline__ void cp_async16(uint32_t dst, const void* src) {
    asm volatile("cp.async.cg.shared.global [%0], [%1], 16;" :: "r"(dst), "l"(src));
}
#define CP_COMMIT() asm volatile("cp.async.commit_group;" ::: "memory")
#define CP_WAIT(n)  asm volatile("cp.async.wait_group %0;" :: "n"(n) : "memory")

// ------------------------- K0: reset tagged h buffer (per replay) -------------------------
__global__ void k_init() {
    int idx = blockIdx.x * blockDim.x + threadIdx.x;
    if (idx < 2 * 8 * 2 * 2048) d_hbuf[idx] = 0u;
}

// ------------------------- K1: embedding gather + concat + bf16 + pad -------------------------
__global__ void k_embed(const int* __restrict__ ids, const int* __restrict__ sids,
                        const float* __restrict__ emb, const float* __restrict__ semb) {
    int m = blockIdx.x;
    int c = threadIdx.x;
    __nv_bfloat16* xp = d_xb + (size_t)m * KP;
    if (c < 300) {
        int id = ids[m];
        int sid = sids[m];
        xp[c]       = __float2bfloat16_rn(emb[(size_t)id * 300 + c]);
        xp[300 + c] = __float2bfloat16_rn(semb[(size_t)sid * 300 + c]);
    } else {
        int z = c - 300;
        xp[600 + z] = __float2bfloat16_rn(0.f);
        xp[620 + z] = __float2bfloat16_rn(0.f);
    }
}

// ------------------------- K1b: weight conversion to bf16 (padded) -------------------------
__global__ void k_wconv(const float* __restrict__ Wf, const float* __restrict__ Wb) {
    int idx = blockIdx.x * blockDim.x + threadIdx.x;
    if (idx >= 2048 * KP) return;
    int row = idx / KP, k = idx - row * KP;
    float v = 0.f;
    if (k < KRAW) v = (row < 1024) ? Wf[row * KRAW + k] : Wb[(row - 1024) * KRAW + k];
    d_wb[idx] = __float2bfloat16_rn(v);
}

// ------------------------- K2: mma.sync bf16 GEMM, cp.async 3-stage (proven 181us) -------------------------
#define APITCH 40
#define STAGE_ELEMS (128 * APITCH)
#define GSMEM_BYTES (3 * 2 * STAGE_ELEMS * 2)

__device__ __forceinline__ void ldm_x4(uint32_t* r, uint32_t addr) {
    asm volatile("ldmatrix.sync.aligned.m8n8.x4.shared.b16 {%0,%1,%2,%3}, [%4];"
                 : "=r"(r[0]), "=r"(r[1]), "=r"(r[2]), "=r"(r[3]) : "r"(addr));
}
__device__ __forceinline__ void mma16816(float* c, const uint32_t* a, const uint32_t* b) {
    asm volatile(
        "mma.sync.aligned.m16n8k16.row.col.f32.bf16.bf16.f32 "
        "{%0,%1,%2,%3}, {%4,%5,%6,%7}, {%8,%9}, {%0,%1,%2,%3};"
        : "+f"(c[0]), "+f"(c[1]), "+f"(c[2]), "+f"(c[3])
        : "r"(a[0]), "r"(a[1]), "r"(a[2]), "r"(a[3]), "r"(b[0]), "r"(b[1]));
}

__global__ void __launch_bounds__(256, 2)
k_gemm_mma(const float* __restrict__ bihf, const float* __restrict__ bhhf,
           const float* __restrict__ bihb, const float* __restrict__ bhhb,
           const int* __restrict__ lengths) {
    extern __shared__ __align__(16) __nv_bfloat16 smem[];
    __nv_bfloat16* sA = smem;
    __nv_bfloat16* sB = smem + 3 * STAGE_ELEMS;

    int tid = threadIdx.x;
    int wid = tid >> 5;
    int lane = tid & 31;
    int warpM = wid & 3;
    int warpN = wid >> 2;
    int m0 = blockIdx.y * 128;
    int n0g = blockIdx.x * 128;
    int dir = n0g >> 10;
    int n0 = n0g & 1023;

    const __nv_bfloat16* xa = d_xb + (size_t)m0 * KP;
    const __nv_bfloat16* wa = d_wb + (size_t)n0g * KP;

    int v0 = tid * 2;
    int r0i = v0 >> 2, j0 = v0 & 3;
    int v1 = v0 + 1;
    int r1i = v1 >> 2, j1 = v1 & 3;

    uint32_t sA0 = smem_u32(&sA[r0i * APITCH + j0 * 8]);
    uint32_t sA1 = smem_u32(&sA[r1i * APITCH + j1 * 8]);
    uint32_t sB0 = smem_u32(&sB[r0i * APITCH + j0 * 8]);
    uint32_t sB1 = smem_u32(&sB[r1i * APITCH + j1 * 8]);
    const uint32_t stageB = STAGE_ELEMS * 2;

    float acc[2][8][4];
#pragma unroll
    for (int mf = 0; mf < 2; mf++)
#pragma unroll
        for (int nf = 0; nf < 8; nf++)
#pragma unroll
            for (int q = 0; q < 4; q++) acc[mf][nf][q] = 0.f;

#pragma unroll
    for (int s = 0; s < 2; s++) {
        const __nv_bfloat16* xan = xa + s * 32;
        const __nv_bfloat16* wan = wa + s * 32;
        cp_async16(sA0 + s * stageB, xan + (size_t)r0i * KP + j0 * 8);
        cp_async16(sA1 + s * stageB, xan + (size_t)r1i * KP + j1 * 8);
        cp_async16(sB0 + s * stageB, wan + (size_t)r0i * KP + j0 * 8);
        cp_async16(sB1 + s * stageB, wan + (size_t)r1i * KP + j1 * 8);
        CP_COMMIT();
    }
    CP_WAIT(1);
    __syncthreads();

    int aRow = warpM * 32 + (lane & 15);
    int aCol = (lane >> 4) << 3;
    int bRowBase = warpN * 64 + ((lane >> 4) << 3) + (lane & 7);
    int bCol = ((lane >> 3) & 1) << 3;

    for (int c = 0; c < 20; c++) {
        int buf = c % 3;
        if (c + 2 < 20) {
            int nb = (c + 2) % 3;
            const __nv_bfloat16* xan = xa + (c + 2) * 32;
            const __nv_bfloat16* wan = wa + (c + 2) * 32;
            cp_async16(sA0 + nb * stageB, xan + (size_t)r0i * KP + j0 * 8);
            cp_async16(sA1 + nb * stageB, xan + (size_t)r1i * KP + j1 * 8);
            cp_async16(sB0 + nb * stageB, wan + (size_t)r0i * KP + j0 * 8);
            cp_async16(sB1 + nb * stageB, wan + (size_t)r1i * KP + j1 * 8);
            CP_COMMIT();
        }
        const __nv_bfloat16* bufA = sA + buf * STAGE_ELEMS;
        const __nv_bfloat16* bufB = sB + buf * STAGE_ELEMS;
#pragma unroll
        for (int ks = 0; ks < 2; ks++) {
            int kc = ks * 16;
            uint32_t af[2][4];
#pragma unroll
            for (int mf = 0; mf < 2; mf++)
                ldm_x4(af[mf], smem_u32(&bufA[(aRow + mf * 16) * APITCH + kc + aCol]));
            uint32_t bf[4][4];
#pragma unroll
            for (int p = 0; p < 4; p++)
                ldm_x4(bf[p], smem_u32(&bufB[(bRowBase + p * 16) * APITCH + kc + bCol]));
#pragma unroll
            for (int mf = 0; mf < 2; mf++)
#pragma unroll
                for (int nf = 0; nf < 8; nf++)
                    mma16816(acc[mf][nf], af[mf], &bf[nf >> 1][(nf & 1) * 2]);
        }
        if (c + 1 < 20) {
            if (c + 2 < 20) { CP_WAIT(1); } else { CP_WAIT(0); }
            __syncthreads();
        }
    }

    const float* bihp = dir ? bihb : bihf;
    const float* bhhp = dir ? bhhb : bhhf;
    int groupID = lane >> 2;
    int qn = (lane & 3) * 2;
#pragma unroll
    for (int mf = 0; mf < 2; mf++) {
#pragma unroll
        for (int mr = 0; mr < 2; mr++) {
            int m = m0 + warpM * 32 + mf * 16 + groupID + mr * 8;
            int b = m >> 8, t = m & 255;
            int row = t;
            if (dir) {
                int len = lengths[b];
                row = (t < len) ? (len - 1 - t) : t;
            }
            float* outp = d_g + ((size_t)dir * M_ + (size_t)row * B_ + b) * G4_;
#pragma unroll
            for (int nf = 0; nf < 8; nf++) {
                int n = n0 + warpN * 64 + nf * 8 + qn;
                float2 o;
                o.x = acc[mf][nf][mr * 2 + 0] + bihp[n] + bhhp[n];
                o.y = acc[mf][nf][mr * 2 + 1] + bihp[n + 1] + bhhp[n + 1];
                *(float2*)(outp + n) = o;
            }
        }
    }
}

// ------------------------- K3: persistent bidirectional LSTM recurrence -------------------------
// R13 tagged-word exchange + R12 tensor-core phase-1 (both proven):
// poll chunk -> bf16 payloads into sHb[kc][batch][unit] -> A frags = 4 LDS.32 -> 32 MMAs.
#define RPITCH 132
__global__ void __launch_bounds__(256, 1)
k_rec(const float* __restrict__ Whh_f, const float* __restrict__ Whh_b,
      const int* __restrict__ lengths) {
    __shared__ float sRed[8 * 8 * RPITCH];            // [kc][batch] pitch 132 (128 gate-rows)
    __shared__ __nv_bfloat16 sHb[8][8][32];           // [kc][batch][unit] bf16

    int tid = threadIdx.x;
    int bx = blockIdx.x;
    int dir = bx >> 6;
    int r6 = bx & 63;
    int bbt = r6 >> 3;
    int ut = r6 & 7;
    int u0 = ut * 32;
    const float* Whh = dir ? Whh_b : Whh_f;
    const float* gbase = d_g + (size_t)dir * M_ * G4_;
    int grp = dir * 8 + bbt;
    unsigned* hbufGrp = d_hbuf + (size_t)grp * 2 * 2048;

    int kc = tid >> 5;     // warp id = k-chunk (h-unit chunk) 0..7
    int lane = tid & 31;
    int g = lane >> 2;     // mma groupID (= batch row for A/D)
    int cc = lane & 3;

    int bb2 = tid >> 5;    // phase-2 batch
    int q2 = lane;         // phase-2 unit offset
    int batch2 = bbt * 8 + bb2;
    int len2 = lengths[batch2];

    // ---- persistent B fragments (R12, proven): Whh rows as bf16x2 regs ----
    uint32_t Bf[16][2][2];
#pragma unroll
    for (int f = 0; f < 16; f++) {
        int r = f * 8 + g;
        int grow = (r >> 5) * 256 + u0 + (r & 31);
        const float* wr = Whh + (size_t)grow * 256 + kc * 32;
#pragma unroll
        for (int q = 0; q < 2; q++) {
            int kb = q * 16 + 2 * cc;
            float2 w01 = *(const float2*)(wr + kb);
            float2 w89 = *(const float2*)(wr + kb + 8);
            Bf[f][q][0] = bf16x2_pack(w01.y, w01.x);
            Bf[f][q][1] = bf16x2_pack(w89.y, w89.x);
        }
    }

    float c = 0.f;
    __syncthreads();

    // preload step 0's gates
    float gpre[4];
    {
        const float* gx = gbase + (size_t)batch2 * G4_;
#pragma unroll
        for (int gg = 0; gg < 4; gg++) gpre[gg] = gx[gg * 256 + u0 + q2];
    }

    float* sOut = &sRed[(kc * 8 + g) * RPITCH + 2 * cc];

    for (int step = 0; step < 256; step++) {
        // next step's gate prefetch (full-step latency cover)
        float gnxt[4];
        if (step + 1 < 256) {
            const float* gx = gbase + ((size_t)(step + 1) * B_ + batch2) * G4_;
#pragma unroll
            for (int gg = 0; gg < 4; gg++) gnxt[gg] = __ldcg(&gx[gg * 256 + u0 + q2]);
        }

        // ---- phase 1 ----
        if (step == 0) {
#pragma unroll
            for (int f = 0; f < 16; f++)
                *(float2*)(sOut + f * 8) = make_float2(0.f, 0.f);
        } else {
            // poll tagged chunk (R13, proven): unit = kc*32+lane, batches 0..7
            int rb = (step - 1) & 1;
            const unsigned* src = hbufGrp + rb * 2048 + kc * 256 + lane * 8;
            unsigned expect = (unsigned)step;
            unsigned w0, w1, w2, w3, w4, w5, w6, w7;
            int tries = 0;
            for (;;) {
                asm volatile("ld.global.cg.v4.u32 {%0,%1,%2,%3}, [%4];"
                             : "=r"(w0), "=r"(w1), "=r"(w2), "=r"(w3)
                             : "l"(src) : "memory");
                asm volatile("ld.global.cg.v4.u32 {%0,%1,%2,%3}, [%4];"
                             : "=r"(w4), "=r"(w5), "=r"(w6), "=r"(w7)
                             : "l"(src + 4) : "memory");
                bool ok = ((w0 & 0xFFFFu) == expect) & ((w1 & 0xFFFFu) == expect)
                        & ((w2 & 0xFFFFu) == expect) & ((w3 & 0xFFFFu) == expect)
                        & ((w4 & 0xFFFFu) == expect) & ((w5 & 0xFFFFu) == expect)
                        & ((w6 & 0xFFFFu) == expect) & ((w7 & 0xFFFFu) == expect);
                if (__all_sync(0xffffffffu, ok)) break;
                if (++tries > 2) __nanosleep(40);
            }
            // scatter bf16 payloads into [batch][unit] tile (warp-private)
            sHb[kc][0][lane] = __ushort_as_bfloat16((unsigned short)(w0 >> 16));
            sHb[kc][1][lane] = __ushort_as_bfloat16((unsigned short)(w1 >> 16));
            sHb[kc][2][lane] = __ushort_as_bfloat16((unsigned short)(w2 >> 16));
            sHb[kc][3][lane] = __ushort_as_bfloat16((unsigned short)(w3 >> 16));
            sHb[kc][4][lane] = __ushort_as_bfloat16((unsigned short)(w4 >> 16));
            sHb[kc][5][lane] = __ushort_as_bfloat16((unsigned short)(w5 >> 16));
            sHb[kc][6][lane] = __ushort_as_bfloat16((unsigned short)(w6 >> 16));
            sHb[kc][7][lane] = __ushort_as_bfloat16((unsigned short)(w7 >> 16));
            __syncwarp();

            // A fragments: row m=batch g, cols k = q*16 + {2cc,2cc+1} and +8 (R12 mapping)
            uint32_t Af[2][2];
#pragma unroll
            for (int q = 0; q < 2; q++) {
                Af[q][0] = *(const uint32_t*)&sHb[kc][g][q * 16 + 2 * cc];
                Af[q][1] = *(const uint32_t*)&sHb[kc][g][q * 16 + 2 * cc + 8];
            }
            float a0[16], a1[16];
            float j0, j1;
#pragma unroll
            for (int f = 0; f < 16; f++) {
                asm volatile(
                    "mma.sync.aligned.m16n8k16.row.col.f32.bf16.bf16.f32 "
                    "{%0,%1,%2,%3}, {%4,%5,%6,%7}, {%8,%9}, {%10,%11,%2,%3};"
                    : "=f"(a0[f]), "=f"(a1[f]), "+f"(j0), "+f"(j1)
                    : "r"(Af[0][0]), "r"(0u), "r"(Af[0][1]), "r"(0u),
                      "r"(Bf[f][0][0]), "r"(Bf[f][0][1]), "f"(0.f), "f"(0.f));
                asm volatile(
                    "mma.sync.aligned.m16n8k16.row.col.f32.bf16.bf16.f32 "
                    "{%0,%1,%2,%3}, {%4,%5,%6,%7}, {%8,%9}, {%0,%1,%2,%3};"
                    : "+f"(a0[f]), "+f"(a1[f]), "+f"(j0), "+f"(j1)
                    : "r"(Af[1][0]), "r"(0u), "r"(Af[1][1]), "r"(0u),
                      "r"(Bf[f][1][0]), "r"(Bf[f][1][1]));
            }
#pragma unroll
            for (int f = 0; f < 16; f++)
                *(float2*)(sOut + f * 8) = make_float2(a0[f], a1[f]);
        }
        __syncthreads();

        // ---- phase 2: gates, cell update (R12, proven) ----
        float gate[4];
#pragma unroll
        for (int gg = 0; gg < 4; gg++) {
            float s = gpre[gg];
#pragma unroll
            for (int kcc = 0; kcc < 8; kcc++)
                s += sRed[(kcc * 8 + bb2) * RPITCH + gg * 32 + q2];
            gate[gg] = s;
        }
        float i_ = sigm(gate[0]);
        float f_ = sigm(gate[1]);
        float gg_ = tanh_ap(gate[2]);
        float o_ = sigm(gate[3]);
        c = f_ * c + i_ * gg_;
        float h = o_ * tanh_ap(c);

        // ---- publish tagged word (R13, proven) ----
        int wbuf = step & 1;
        __nv_bfloat16 hb16 = __float2bfloat16_rn(h);
        unsigned wword = ((unsigned)*(unsigned short*)&hb16 << 16) | (unsigned)(step + 1);
        __stcg(&hbufGrp[wbuf * 2048 + (u0 + q2) * 8 + bb2], wword);

        __syncthreads();   // sRed WAR across warps (next step's writes vs this step's reads)

        // d_h store off the critical path
        int tout = dir ? ((step < len2) ? (len2 - 1 - step) : step) : step;
        d_h[((size_t)batch2 * T_ + tout) * 512 + dir * 256 + u0 + q2] = h;

#pragma unroll
        for (int gg = 0; gg < 4; gg++) gpre[gg] = gnxt[gg];
    }
}

// ------------------------- K4: emissions = h . Wlin^T + blin -------------------------
__global__ void __launch_bounds__(128)
k_emis(const float* __restrict__ Wlin, const float* __restrict__ blin) {
    __shared__ float sW[15 * 516];
    __shared__ float sh[8 * 512];
    int tid = threadIdx.x;
    for (int i = tid; i < 15 * 512; i += 128) {
        int l = i >> 9, k = i & 511;
        sW[l * 516 + k] = Wlin[i];
    }
    int m0 = blockIdx.x * 8;
    const float4* hsrc = (const float4*)(d_h + (size_t)m0 * 512);
    for (int i = tid; i < 8 * 512 / 4; i += 128)
        ((float4*)sh)[i] = hsrc[i];
    __syncthreads();

    int r = tid >> 4, l = tid & 15;
    if (l < 15) {
        float s = blin[l];
        const float* hw = sh + r * 512;
        const float* ww = sW + l * 516;
#pragma unroll 8
        for (int k = 0; k < 512; k += 4) {
            float4 hv = *(const float4*)(hw + k);
            float4 wv = *(const float4*)(ww + k);
            s += hv.x * wv.x + hv.y * wv.y + hv.z * wv.z + hv.w * wv.w;
        }
        d_emis[(size_t)(m0 + r) * L_ + l] = s;
    }
}

// ------------------------- K5: CRF NLL per sequence -------------------------
__global__ void k_crf(const int* __restrict__ lengths, const int* __restrict__ labels,
                      const float* __restrict__ start_t, const float* __restrict__ end_t,
                      const float* __restrict__ trans) {
    int b = blockIdx.x;
    int lane = threadIdx.x;
    int len = lengths[b];
    const float* em = d_emis + (size_t)b * T_ * L_;
    int j = (lane < L_) ? lane : 0;

    float tr[L_];
#pragma unroll
    for (int i = 0; i < L_; i++) tr[i] = trans[i * L_ + j];

    float alpha = start_t[j] + em[j];
    for (int t = 1; t < T_; t++) {
        float v[L_], mx = -1e30f;
#pragma unroll
        for (int i = 0; i < L_; i++) {
            float av = __shfl_sync(0xffffffffu, alpha, i);
            v[i] = av + tr[i];
            mx = fmaxf(mx, v[i]);
        }
        float s = 0.f;
#pragma unroll
        for (int i = 0; i < L_; i++) s += __expf(v[i] - mx);
        float nxt = mx + __logf(s) + em[t * L_ + j];
        if (t < len) alpha = nxt;
    }
    float vv = (lane < L_) ? (alpha + end_t[lane]) : -1e30f;
    float mx = vv;
#pragma unroll
    for (int o = 16; o; o >>= 1) mx = fmaxf(mx, __shfl_xor_sync(0xffffffffu, mx, o));
    float se = (lane < L_) ? __expf(vv - mx) : 0.f;
#pragma unroll
    for (int o = 16; o; o >>= 1) se += __shfl_xor_sync(0xffffffffu, se, o);
    float den = mx + __logf(se);

    const int* tg = labels + b * T_;
    float em_s = 0.f, tr_s = 0.f;
    for (int t = lane; t < T_; t += 32) {
        if (t < len) {
            em_s += em[t * L_ + tg[t]];
            if (t >= 1) tr_s += trans[tg[t - 1] * L_ + tg[t]];
        }
    }
#pragma unroll
    for (int o = 16; o; o >>= 1) {
        em_s += __shfl_xor_sync(0xffffffffu, em_s, o);
        tr_s += __shfl_xor_sync(0xffffffffu, tr_s, o);
    }
    if (lane == 0) {
        float num = start_t[tg[0]] + em_s + tr_s + end_t[tg[len - 1]];
        d_partial[b] = num - den;
    }
}

// ------------------------- K6: deterministic final sum -------------------------
__global__ void k_final(float* __restrict__ out) {
    float s = 0.f;
#pragma unroll
    for (int b = 0; b < B_; b++) s += d_partial[b];
    out[0] = -s;
}

// ------------------------- launch -------------------------
extern "C" void kernel_launch(void* const* d_in, const int* in_sizes, int n_in,
                              void* d_out, int out_size) {
    const int*   input_ids    = (const int*)d_in[0];
    const int*   lengths      = (const int*)d_in[1];
    const int*   softword_ids = (const int*)d_in[2];
    const int*   label_ids    = (const int*)d_in[3];
    const float* emb          = (const float*)d_in[4];
    const float* soft_emb     = (const float*)d_in[5];
    const float* Wih_f        = (const float*)d_in[6];
    const float* Whh_f        = (const float*)d_in[7];
    const float* bih_f        = (const float*)d_in[8];
    const float* bhh_f        = (const float*)d_in[9];
    const float* Wih_b        = (const float*)d_in[10];
    const float* Whh_b        = (const float*)d_in[11];
    const float* bih_b        = (const float*)d_in[12];
    const float* bhh_b        = (const float*)d_in[13];
    const float* Wlin         = (const float*)d_in[14];
    const float* blin         = (const float*)d_in[15];
    const float* start_t      = (const float*)d_in[16];
    const float* end_t        = (const float*)d_in[17];
    const float* trans        = (const float*)d_in[18];
    float* out = (float*)d_out;

    cudaFuncSetAttribute(k_gemm_mma, cudaFuncAttributeMaxDynamicSharedMemorySize, GSMEM_BYTES);

    k_init<<<64, 1024>>>();
    k_embed<<<M_, 320>>>(input_ids, softword_ids, emb, soft_emb);
    k_wconv<<<(2048 * KP + 511) / 512, 512>>>(Wih_f, Wih_b);
    dim3 g2(16, 128);
    k_gemm_mma<<<g2, 256, GSMEM_BYTES>>>(bih_f, bhh_f, bih_b, bhh_b, lengths);
    k_rec<<<128, 256>>>(Whh_f, Whh_b, lengths);
    k_emis<<<2048, 128>>>(Wlin, blin);
    k_crf<<<B_, 32>>>(lengths, label_ids, start_t, end_t, trans);
    k_final<<<1, 1>>>(out);
}